// round 3
// baseline (speedup 1.0000x reference)
#include <cuda_runtime.h>

// FokkerPlanck2D step: f_new = max(0, f + dt*rhs), 9-point stencil with
// per-pixel weights from A (drift) and D (diffusion) at neighbor sites.
// Zero (vacuum) boundaries.
//
// Structure: i-pencil blocks, 128 threads x float4 = full 512-wide row,
// NBATCH=4 batches share coefficient rows. f rows live in a 4-deep shared
// memory ring per batch (with zero halo cells), loaded with a one-iteration
// prefetch (LDG at top of iter i for row i+2, STS at bottom, one barrier).
// Weights are recomputed each i-step from A/D (L1-resident re-reads).

static constexpr int NXC    = 512;
static constexpr int NYC    = 512;
static constexpr int ICH    = 16;         // i-rows per block
static constexpr int NBATCH = 4;          // batches per block
static constexpr int TPB    = NYC / 4;    // 128 threads
static constexpr int ROWW   = 520;        // padded smem row: data at [4..515], halos [3],[516]

__device__ __forceinline__ void win6_g(const float* __restrict__ row, int j0,
                                       bool Lg, bool Rg, float v[6]) {
    // v[m] = row[j0 + m - 1], zero-filled outside [0, NYC)
    const float4 m4 = __ldg(reinterpret_cast<const float4*>(row + j0));
    v[0] = Lg ? __ldg(row + j0 - 1) : 0.0f;
    v[1] = m4.x; v[2] = m4.y; v[3] = m4.z; v[4] = m4.w;
    v[5] = Rg ? __ldg(row + j0 + 4) : 0.0f;
}

__global__ __launch_bounds__(TPB, 6)
void fp2d_step_kernel(const float* __restrict__ f,
                      const float* __restrict__ A,
                      const float* __restrict__ D,
                      const float* __restrict__ dtp,
                      float* __restrict__ out) {
    __shared__ __align__(16) float sf[NBATCH][4][ROWW];

    const int tid = threadIdx.x;
    const int j0  = tid * 4;
    const bool L  = (tid > 0);
    const bool R  = (tid < TPB - 1);
    const int i0  = blockIdx.x * ICH;
    const long b0 = (long)blockIdx.y * NBATCH;

    const float dt  = __ldg(dtp);
    const float hdt = 0.5f  * dt;
    const float qdt = 0.25f * dt;

    const long plane = (long)NXC * NYC;
    const float* A0 = A;
    const float* A1 = A + plane;
    const float* D0 = D;
    const float* D1 = D + plane;
    const float* D2 = D + 2 * plane;

    // ---------------- prologue: rows i0-1, i0, i0+1 into the ring ----------------
    #pragma unroll
    for (int dr = -1; dr <= 1; ++dr) {
        const int r = i0 + dr;
        const int s = r & 3;               // -1 & 3 == 3
        #pragma unroll
        for (int b = 0; b < NBATCH; ++b) {
            float4 v = make_float4(0.f, 0.f, 0.f, 0.f);
            if (r >= 0 && r < NXC)
                v = __ldg(reinterpret_cast<const float4*>(f + (b0 + b) * plane + (long)r * NYC + j0));
            *reinterpret_cast<float4*>(&sf[b][s][4 + j0]) = v;
            if (tid == 0)       sf[b][s][3]       = 0.f;
            if (tid == TPB - 1) sf[b][s][4 + NYC] = 0.f;
        }
    }
    __syncthreads();

    const int iend = i0 + ICH;
    for (int i = i0; i < iend; ++i) {
        // 1) stage f row i+2 into registers (consumed via STS at the bottom)
        float4 st[NBATCH];
        const int r2 = i + 2;
        const bool do_stage = (r2 <= iend);     // last needed row is iend (= last i + 1)
        if (do_stage) {
            #pragma unroll
            for (int b = 0; b < NBATCH; ++b) {
                st[b] = make_float4(0.f, 0.f, 0.f, 0.f);
                if (r2 < NXC)
                    st[b] = __ldg(reinterpret_cast<const float4*>(f + (b0 + b) * plane + (long)r2 * NYC + j0));
            }
        }

        // 2) weights for output row i (fresh each iteration; coeff rows are L1-hot)
        float wxp[4], wxm[4], wdp[6], wdm[6], ccc[4], cyp[4], cym[4];
        {
            const int ip = i + 1;
            if (ip < NXC) {
                const float4 a0 = __ldg(reinterpret_cast<const float4*>(A0 + (long)ip * NYC + j0));
                const float4 d0 = __ldg(reinterpret_cast<const float4*>(D0 + (long)ip * NYC + j0));
                wxp[0] = hdt * (d0.x - a0.x);
                wxp[1] = hdt * (d0.y - a0.y);
                wxp[2] = hdt * (d0.z - a0.z);
                wxp[3] = hdt * (d0.w - a0.w);
                float w[6];
                win6_g(D2 + (long)ip * NYC, j0, L, R, w);
                #pragma unroll
                for (int m = 0; m < 6; ++m) wdp[m] = qdt * w[m];
            } else {
                #pragma unroll
                for (int k = 0; k < 4; ++k) wxp[k] = 0.f;
                #pragma unroll
                for (int m = 0; m < 6; ++m) wdp[m] = 0.f;
            }
        }
        {
            const int im = i - 1;
            if (im >= 0) {
                const float4 a0 = __ldg(reinterpret_cast<const float4*>(A0 + (long)im * NYC + j0));
                const float4 d0 = __ldg(reinterpret_cast<const float4*>(D0 + (long)im * NYC + j0));
                wxm[0] = hdt * (d0.x + a0.x);
                wxm[1] = hdt * (d0.y + a0.y);
                wxm[2] = hdt * (d0.z + a0.z);
                wxm[3] = hdt * (d0.w + a0.w);
                float w[6];
                win6_g(D2 + (long)im * NYC, j0, L, R, w);
                #pragma unroll
                for (int m = 0; m < 6; ++m) wdm[m] = qdt * w[m];
            } else {
                #pragma unroll
                for (int k = 0; k < 4; ++k) wxm[k] = 0.f;
                #pragma unroll
                for (int m = 0; m < 6; ++m) wdm[m] = 0.f;
            }
        }
        {
            const float4 d0 = __ldg(reinterpret_cast<const float4*>(D0 + (long)i * NYC + j0));
            float d1w[6], a1w[6];
            win6_g(D1 + (long)i * NYC, j0, L, R, d1w);
            win6_g(A1 + (long)i * NYC, j0, L, R, a1w);
            const float d0v[4] = {d0.x, d0.y, d0.z, d0.w};
            #pragma unroll
            for (int k = 0; k < 4; ++k) {
                ccc[k] = 1.0f - dt * (d0v[k] + d1w[k + 1]);
                cyp[k] = hdt * (d1w[k + 2] - a1w[k + 2]);
                cym[k] = hdt * (d1w[k]     + a1w[k]);
            }
        }

        // 3) compute + streaming-store outputs for row i from smem ring
        const int sup = (i + 1) & 3;
        const int scn =  i      & 3;
        const int sdn = (i - 1) & 3;
        #pragma unroll
        for (int b = 0; b < NBATCH; ++b) {
            const float* rup = &sf[b][sup][4 + j0];
            const float* rcn = &sf[b][scn][4 + j0];
            const float* rdn = &sf[b][sdn][4 + j0];
            const float4 u4 = *reinterpret_cast<const float4*>(rup);
            const float4 c4 = *reinterpret_cast<const float4*>(rcn);
            const float4 d4 = *reinterpret_cast<const float4*>(rdn);
            const float fu[6] = {rup[-1], u4.x, u4.y, u4.z, u4.w, rup[4]};
            const float fc[6] = {rcn[-1], c4.x, c4.y, c4.z, c4.w, rcn[4]};
            const float fd[6] = {rdn[-1], d4.x, d4.y, d4.z, d4.w, rdn[4]};
            float rv[4];
            #pragma unroll
            for (int k = 0; k < 4; ++k) {
                float v = ccc[k] * fc[k + 1];
                v += wxp[k] * fu[k + 1];
                v += wxm[k] * fd[k + 1];
                v += cyp[k] * fc[k + 2];
                v += cym[k] * fc[k];
                v += wdp[k + 2] * fu[k + 2];
                v -= wdp[k]     * fu[k];
                v -= wdm[k + 2] * fd[k + 2];
                v += wdm[k]     * fd[k];
                rv[k] = fmaxf(v, 0.0f);
            }
            float4 res;
            res.x = rv[0]; res.y = rv[1]; res.z = rv[2]; res.w = rv[3];
            __stcs(reinterpret_cast<float4*>(out + (b0 + b) * plane + (long)i * NYC + j0), res);
        }

        // 4) commit staged row i+2 into the ring (slot held row i-2: dead this iter)
        if (do_stage) {
            const int s2 = r2 & 3;
            #pragma unroll
            for (int b = 0; b < NBATCH; ++b) {
                *reinterpret_cast<float4*>(&sf[b][s2][4 + j0]) = st[b];
                if (tid == 0)       sf[b][s2][3]       = 0.f;
                if (tid == TPB - 1) sf[b][s2][4 + NYC] = 0.f;
            }
        }
        __syncthreads();
    }
}

extern "C" void kernel_launch(void* const* d_in, const int* in_sizes, int n_in,
                              void* d_out, int out_size) {
    const float* f  = (const float*)d_in[0];
    const float* A  = (const float*)d_in[1];
    const float* D  = (const float*)d_in[2];
    const float* dt = (const float*)d_in[3];
    float* out = (float*)d_out;

    const int plane = NXC * NYC;
    const int B = in_sizes[0] / plane;   // 128

    dim3 grid(NXC / ICH, B / NBATCH);    // (32, 32)
    fp2d_step_kernel<<<grid, TPB>>>(f, A, D, dt, out);
}

// round 4
// speedup vs baseline: 1.6218x; 1.6218x over previous
#include <cuda_runtime.h>

// FokkerPlanck2D step: f_new = max(0, f + dt*rhs), 9-point stencil with
// per-pixel weights from A (drift) and D (diffusion) at neighbor sites:
//   center  : 1 - dt*(D0+D1)            at (i,j)
//   (+1, 0) : dt*0.5*(D0 - A0)          at (i+1,j)
//   (-1, 0) : dt*0.5*(D0 + A0)          at (i-1,j)
//   ( 0,+1) : dt*0.5*(D1 - A1)          at (i,j+1)
//   ( 0,-1) : dt*0.5*(D1 + A1)          at (i,j-1)
//   diagonals: +-0.25*dt*D2 at the diagonal site
// Zero (vacuum) boundaries.
//
// Structure (proven fastest in R1): i-pencil blocks, 128 threads x float4 =
// full 512-wide row, NBATCH=4 batches share coefficient rows, f rows rotate
// through 6-wide register windows. R4 change: all weights are recomputed per
// iteration from L1-hot coefficient rows (no register staging pipelines),
// cutting ~32 regs so 4 blocks/SM fit (16 warps vs 12). ICH=32 -> grid 512
// = one full wave at 4 blocks/SM.

static constexpr int NXC    = 512;
static constexpr int NYC    = 512;
static constexpr int ICH    = 32;         // i-rows per block
static constexpr int NBATCH = 4;          // batches per block
static constexpr int TPB    = NYC / 4;    // 128 threads

__device__ __forceinline__ void win6_g(const float* __restrict__ row, int j0,
                                       bool Lg, bool Rg, float v[6]) {
    // v[m] = row[j0 + m - 1], zero-filled outside [0, NYC)
    const float4 m4 = __ldg(reinterpret_cast<const float4*>(row + j0));
    v[0] = Lg ? __ldg(row + j0 - 1) : 0.0f;
    v[1] = m4.x; v[2] = m4.y; v[3] = m4.z; v[4] = m4.w;
    v[5] = Rg ? __ldg(row + j0 + 4) : 0.0f;
}

__global__ __launch_bounds__(TPB, 4)
void fp2d_step_kernel(const float* __restrict__ f,
                      const float* __restrict__ A,
                      const float* __restrict__ D,
                      const float* __restrict__ dtp,
                      float* __restrict__ out) {
    const int tid = threadIdx.x;
    const int j0  = tid * 4;
    const bool L  = (tid > 0);
    const bool R  = (tid < TPB - 1);
    const int i0  = blockIdx.x * ICH;
    const long b0 = (long)blockIdx.y * NBATCH;

    const float dt  = __ldg(dtp);
    const float hdt = 0.5f  * dt;
    const float qdt = 0.25f * dt;

    const long plane = (long)NXC * NYC;
    const float* A0 = A;
    const float* A1 = A + plane;
    const float* D0 = D;
    const float* D1 = D + plane;
    const float* D2 = D + 2 * plane;

    // f windows: [m] = f[row][j0+m-1], rotated along i
    float fm[NBATCH][6], fc[NBATCH][6], fp[NBATCH][6];

    // ---------------- prologue: f rows i0-1 and i0 ----------------
    {
        const int r = i0 - 1;
        if (r >= 0) {
            const float* frow = f + (long)r * NYC;
            #pragma unroll
            for (int b = 0; b < NBATCH; ++b)
                win6_g(frow + (b0 + b) * plane, j0, L, R, fm[b]);
        } else {
            #pragma unroll
            for (int b = 0; b < NBATCH; ++b)
                #pragma unroll
                for (int m = 0; m < 6; ++m) fm[b][m] = 0.0f;
        }
        const float* frow = f + (long)i0 * NYC;
        #pragma unroll
        for (int b = 0; b < NBATCH; ++b)
            win6_g(frow + (b0 + b) * plane, j0, L, R, fc[b]);
    }

    // ---------------- main i-march ----------------
    for (int i = i0; i < i0 + ICH; ++i) {
        const int ip = i + 1;
        const int im = i - 1;
        const bool up_ok = (ip < NXC);
        const bool dn_ok = (im >= 0);

        // 1) load f row i+1 (the only DRAM-new data this iteration)
        if (up_ok) {
            const float* frow = f + (long)ip * NYC;
            #pragma unroll
            for (int b = 0; b < NBATCH; ++b)
                win6_g(frow + (b0 + b) * plane, j0, L, R, fp[b]);
        } else {
            #pragma unroll
            for (int b = 0; b < NBATCH; ++b)
                #pragma unroll
                for (int m = 0; m < 6; ++m) fp[b][m] = 0.0f;
        }

        // 2) weights for output row i, recomputed from L1-hot coefficient rows
        float wxp[4], wxm[4], wdp[6], wdm[6], ccc[4], cyp[4], cym[4];
        if (up_ok) {
            const float4 a0 = __ldg(reinterpret_cast<const float4*>(A0 + (long)ip * NYC + j0));
            const float4 d0 = __ldg(reinterpret_cast<const float4*>(D0 + (long)ip * NYC + j0));
            wxp[0] = hdt * (d0.x - a0.x);
            wxp[1] = hdt * (d0.y - a0.y);
            wxp[2] = hdt * (d0.z - a0.z);
            wxp[3] = hdt * (d0.w - a0.w);
            float w[6];
            win6_g(D2 + (long)ip * NYC, j0, L, R, w);
            #pragma unroll
            for (int m = 0; m < 6; ++m) wdp[m] = qdt * w[m];
        } else {
            #pragma unroll
            for (int k = 0; k < 4; ++k) wxp[k] = 0.f;
            #pragma unroll
            for (int m = 0; m < 6; ++m) wdp[m] = 0.f;
        }
        if (dn_ok) {
            const float4 a0 = __ldg(reinterpret_cast<const float4*>(A0 + (long)im * NYC + j0));
            const float4 d0 = __ldg(reinterpret_cast<const float4*>(D0 + (long)im * NYC + j0));
            wxm[0] = hdt * (d0.x + a0.x);
            wxm[1] = hdt * (d0.y + a0.y);
            wxm[2] = hdt * (d0.z + a0.z);
            wxm[3] = hdt * (d0.w + a0.w);
            float w[6];
            win6_g(D2 + (long)im * NYC, j0, L, R, w);
            #pragma unroll
            for (int m = 0; m < 6; ++m) wdm[m] = qdt * w[m];
        } else {
            #pragma unroll
            for (int k = 0; k < 4; ++k) wxm[k] = 0.f;
            #pragma unroll
            for (int m = 0; m < 6; ++m) wdm[m] = 0.f;
        }
        {
            const float4 d0 = __ldg(reinterpret_cast<const float4*>(D0 + (long)i * NYC + j0));
            float d1w[6], a1w[6];
            win6_g(D1 + (long)i * NYC, j0, L, R, d1w);
            win6_g(A1 + (long)i * NYC, j0, L, R, a1w);
            const float d0v[4] = {d0.x, d0.y, d0.z, d0.w};
            #pragma unroll
            for (int k = 0; k < 4; ++k) {
                ccc[k] = 1.0f - dt * (d0v[k] + d1w[k + 1]);
                cyp[k] = hdt * (d1w[k + 2] - a1w[k + 2]);
                cym[k] = hdt * (d1w[k]     + a1w[k]);
            }
        }

        // 3) compute + streaming-store outputs for row i
        #pragma unroll
        for (int b = 0; b < NBATCH; ++b) {
            float rv[4];
            #pragma unroll
            for (int k = 0; k < 4; ++k) {
                const int j = k + 1;  // window index of column j0+k
                float v = ccc[k] * fc[b][j];
                v += wxp[k] * fp[b][j];
                v += wxm[k] * fm[b][j];
                v += cyp[k] * fc[b][j + 1];
                v += cym[k] * fc[b][j - 1];
                v += wdp[k + 2] * fp[b][k + 2];
                v -= wdp[k]     * fp[b][k];
                v -= wdm[k + 2] * fm[b][k + 2];
                v += wdm[k]     * fm[b][k];
                rv[k] = fmaxf(v, 0.0f);
            }
            float4 res;
            res.x = rv[0]; res.y = rv[1]; res.z = rv[2]; res.w = rv[3];
            __stcs(reinterpret_cast<float4*>(out + (b0 + b) * plane + (long)i * NYC + j0), res);
        }

        // 4) rotate f windows (fp -> fc -> fm)
        #pragma unroll
        for (int b = 0; b < NBATCH; ++b)
            #pragma unroll
            for (int m = 0; m < 6; ++m) {
                fm[b][m] = fc[b][m];
                fc[b][m] = fp[b][m];
            }
    }
}

extern "C" void kernel_launch(void* const* d_in, const int* in_sizes, int n_in,
                              void* d_out, int out_size) {
    const float* f  = (const float*)d_in[0];
    const float* A  = (const float*)d_in[1];
    const float* D  = (const float*)d_in[2];
    const float* dt = (const float*)d_in[3];
    float* out = (float*)d_out;

    const int plane = NXC * NYC;
    const int B = in_sizes[0] / plane;   // 128

    dim3 grid(NXC / ICH, B / NBATCH);    // (16, 32) = 512 blocks
    fp2d_step_kernel<<<grid, TPB>>>(f, A, D, dt, out);
}